// round 4
// baseline (speedup 1.0000x reference)
#include <cuda_runtime.h>

#define NB 32
#define GRID_N 128
#define CIN 32
#define COUT 32
#define TDIM 256
#define MM 17
#define KY_TOT 34   // 17 top rows + 17 bottom rows

// Scratch (allocation-free): device globals.
// X1: [(b*17+kx)*128 + y]*32 + c   (partial DFT over x)
// Y1: [(b*128+y)*17 + kx]*32 + o   (after mid stage, inverse over ky done)
__device__ float2 g_X1[NB * MM * GRID_N * CIN];
__device__ float2 g_Y1[NB * GRID_N * MM * COUT];
__device__ float2 g_TS[NB * KY_TOT];

// ---------------------------------------------------------------------------
// K0: time-modulation scales  t1 = t_emb @ (k1r + i k1i), t2 likewise. (B,17)
// ---------------------------------------------------------------------------
__global__ void k0_tscale(const float* __restrict__ t_emb,
                          const float* __restrict__ k1r, const float* __restrict__ k1i,
                          const float* __restrict__ k2r, const float* __restrict__ k2i) {
    int b = blockIdx.x;
    int tid = threadIdx.x;           // 64 threads
    int which = tid >> 5;            // 0 -> t1, 1 -> t2
    int m = tid & 31;
    if (m >= MM) return;
    const float* kr = which ? k2r : k1r;
    const float* ki = which ? k2i : k1i;
    const float* te = t_emb + b * TDIM;
    float ar = 0.f, ai = 0.f;
    #pragma unroll 4
    for (int d = 0; d < TDIM; ++d) {
        float v = te[d];
        ar += v * kr[d * MM + m];
        ai += v * ki[d * MM + m];
    }
    g_TS[b * KY_TOT + which * MM + m] = make_float2(ar, ai);
}

// ---------------------------------------------------------------------------
// K1: partial DFT over x (real input), 17 modes, scaled by 1/16384.
// One block per (b, y). Warp-uniform kx -> twiddle broadcast.
// ---------------------------------------------------------------------------
__global__ void k1_dftx(const float* __restrict__ x) {
    __shared__ float  xs[GRID_N * CIN];   // 16 KB
    __shared__ float2 tw[GRID_N];         // e^{+2pi i t/128}
    int b = blockIdx.x >> 7, y = blockIdx.x & 127;
    int tid = threadIdx.x;

    const float* xrow = x + (size_t)(b * GRID_N + y) * GRID_N * CIN;
    for (int i = tid; i < GRID_N * CIN; i += 256) xs[i] = xrow[i];
    if (tid < 128) {
        float s, c;
        sincospif(tid * (1.0f / 64.0f), &s, &c);   // angle = 2*pi*t/128
        tw[tid] = make_float2(c, s);
    }
    __syncthreads();

    const float scale = 1.0f / 16384.0f;
    for (int idx = tid; idx < MM * CIN; idx += 256) {
        int kx = idx >> 5, c = idx & 31;
        float ar = 0.f, ai = 0.f;
        int t = 0;
        #pragma unroll 4
        for (int xi = 0; xi < GRID_N; ++xi) {
            float v = xs[xi * CIN + c];
            float2 w = tw[t];
            ar += v * w.x;      // e^{-i theta}: (c, -s)
            ai -= v * w.y;
            t = (t + kx) & 127;
        }
        g_X1[((b * MM + kx) * GRID_N + y) * CIN + c] = make_float2(ar * scale, ai * scale);
    }
}

// ---------------------------------------------------------------------------
// K2 (fused): per (b, kx):
//   X2[ky,c]  = sum_y X1[y,c] e^{-2pi i ky y/128}   (34 kept rows)
//   Z[ky,o]   = t[ky] * sum_c X2[ky,c] * w[ky_i,kx,c,o]   (complex)
//   Y1[y,o]   = sum_ky Z[ky,o] e^{+2pi i ky y/128}  (all 128 y)
// sZ aliases sX (dead after step 1) to stay under 48 KB static smem.
// ---------------------------------------------------------------------------
__global__ void k2_mid(const float* __restrict__ w1r, const float* __restrict__ w1i,
                       const float* __restrict__ w2r, const float* __restrict__ w2i) {
    __shared__ float2 sX [GRID_N * CIN];   // 32 KB (aliased by sZ after sync)
    __shared__ float2 sX2[KY_TOT * CIN];   // 8.5 KB
    __shared__ float2 tw [GRID_N];         // 1 KB
    __shared__ float2 sT [KY_TOT];
    float2* sZ = sX;                        // reuse: sX dead after step 1

    int b  = blockIdx.x / MM;
    int kx = blockIdx.x % MM;
    int tid = threadIdx.x;

    const float2* src = g_X1 + (size_t)(b * MM + kx) * GRID_N * CIN;
    for (int i = tid; i < GRID_N * CIN; i += 256) sX[i] = src[i];
    if (tid < 128) {
        float s, c;
        sincospif(tid * (1.0f / 64.0f), &s, &c);
        tw[tid] = make_float2(c, s);
    }
    if (tid < KY_TOT) sT[tid] = g_TS[b * KY_TOT + tid];
    __syncthreads();

    // step 1: DFT over y onto the 34 kept rows
    for (int idx = tid; idx < KY_TOT * CIN; idx += 256) {
        int kyi = idx >> 5, c = idx & 31;
        int ky = (kyi < MM) ? kyi : (94 + kyi);   // bottom block rows 111..127
        float ar = 0.f, ai = 0.f;
        int t = 0;
        #pragma unroll 4
        for (int yy = 0; yy < GRID_N; ++yy) {
            float2 a = sX[yy * CIN + c];
            float2 w = tw[t];
            // a * e^{-i theta} = a * (w.x, -w.y)
            ar += a.x * w.x + a.y * w.y;
            ai += a.y * w.x - a.x * w.y;
            t = (t + ky) & 127;
        }
        sX2[idx] = make_float2(ar, ai);
    }
    __syncthreads();

    // step 2: complex channel mix + time scale  -> sZ (aliases sX)
    for (int idx = tid; idx < KY_TOT * COUT; idx += 256) {
        int kyi = idx >> 5, o = idx & 31;
        const float* wr; const float* wi; int iw;
        if (kyi < MM) { wr = w1r; wi = w1i; iw = kyi; }
        else          { wr = w2r; wi = w2i; iw = kyi - MM; }
        size_t base = ((size_t)(iw * MM + kx) * CIN) * COUT + o;
        float ar = 0.f, ai = 0.f;
        #pragma unroll 4
        for (int c = 0; c < CIN; ++c) {
            float2 a = sX2[kyi * CIN + c];
            float wre = wr[base + (size_t)c * COUT];
            float wim = wi[base + (size_t)c * COUT];
            ar += a.x * wre - a.y * wim;
            ai += a.x * wim + a.y * wre;
        }
        float2 ts = sT[kyi];
        sZ[idx] = make_float2(ar * ts.x - ai * ts.y, ar * ts.y + ai * ts.x);
    }
    __syncthreads();

    // step 3: inverse DFT over ky to all 128 y
    for (int idx = tid; idx < GRID_N * COUT; idx += 256) {
        int yy = idx >> 5, o = idx & 31;
        float ar = 0.f, ai = 0.f;
        #pragma unroll
        for (int kyi = 0; kyi < KY_TOT; ++kyi) {
            int ky = (kyi < MM) ? kyi : (94 + kyi);
            int t = (ky * yy) & 127;
            float2 z = sZ[kyi * COUT + o];
            float2 w = tw[t];                  // e^{+i theta}
            ar += z.x * w.x - z.y * w.y;
            ai += z.x * w.y + z.y * w.x;
        }
        g_Y1[((b * GRID_N + yy) * MM + kx) * COUT + o] = make_float2(ar, ai);
    }
}

// ---------------------------------------------------------------------------
// K3: inverse over x with irfft (C2R) semantics:
//   out[x] = Re(Y[0]) + 2 * sum_{kx=1..16} Re(Y[kx] * e^{+2pi i kx x/128})
// One block per (b, y); Y row hoisted into registers (33 floats/thread).
// ---------------------------------------------------------------------------
__global__ void k3_idftx(float* __restrict__ out) {
    __shared__ float2 sY[MM * COUT];   // 4.25 KB
    __shared__ float2 tw[GRID_N];
    int b = blockIdx.x >> 7, y = blockIdx.x & 127;
    int tid = threadIdx.x;

    const float2* src = g_Y1 + (size_t)(b * GRID_N + y) * MM * COUT;
    for (int i = tid; i < MM * COUT; i += 256) sY[i] = src[i];
    if (tid < 128) {
        float s, c;
        sincospif(tid * (1.0f / 64.0f), &s, &c);
        tw[tid] = make_float2(c, s);
    }
    __syncthreads();

    int o  = tid & 31;
    int xg = tid >> 5;   // 0..7

    float yr[MM], yi[MM];
    yr[0] = sY[o].x;     // Im of bin 0 ignored (C2R convention); bin 64 is zero
    yi[0] = 0.f;
    #pragma unroll
    for (int k = 1; k < MM; ++k) {
        float2 v = sY[k * COUT + o];
        yr[k] = 2.f * v.x;
        yi[k] = 2.f * v.y;
    }

    float* orow = out + (size_t)(b * GRID_N + y) * GRID_N * COUT;
    for (int x = xg; x < GRID_N; x += 8) {
        float acc = yr[0];
        #pragma unroll
        for (int k = 1; k < MM; ++k) {
            int t = (k * x) & 127;
            float2 w = tw[t];
            acc += yr[k] * w.x - yi[k] * w.y;   // Re(Y * e^{+i theta})
        }
        orow[(size_t)x * COUT + o] = acc;
    }
}

// ---------------------------------------------------------------------------
extern "C" void kernel_launch(void* const* d_in, const int* in_sizes, int n_in,
                              void* d_out, int out_size) {
    const float* x     = (const float*)d_in[0];
    const float* t_emb = (const float*)d_in[1];
    const float* w1r   = (const float*)d_in[2];
    const float* w1i   = (const float*)d_in[3];
    const float* w2r   = (const float*)d_in[4];
    const float* w2i   = (const float*)d_in[5];
    const float* k1r   = (const float*)d_in[6];
    const float* k1i   = (const float*)d_in[7];
    const float* k2r   = (const float*)d_in[8];
    const float* k2i   = (const float*)d_in[9];
    float* out = (float*)d_out;

    k0_tscale<<<NB, 64>>>(t_emb, k1r, k1i, k2r, k2i);
    k1_dftx  <<<NB * GRID_N, 256>>>(x);
    k2_mid   <<<NB * MM,     256>>>(w1r, w1i, w2r, w2i);
    k3_idftx <<<NB * GRID_N, 256>>>(out);
}

// round 5
// speedup vs baseline: 1.6045x; 1.6045x over previous
#include <cuda_runtime.h>

#define NB 32
#define GRID_N 128
#define CIN 32
#define COUT 32
#define TDIM 256
#define MM 17
#define KY_TOT 34   // 17 top rows + 17 bottom rows

// Scratch (allocation-free): device globals.
// X1: [(b*17+kx)*128 + y]*32 + c   (partial DFT over x)
// Y1: [(b*128+y)*17 + kx]*32 + o   (after mid stage, inverse over ky done)
__device__ float2 g_X1[NB * MM * GRID_N * CIN];
__device__ float2 g_Y1[NB * GRID_N * MM * COUT];
__device__ float2 g_TS[NB * KY_TOT];

// ---------------------------------------------------------------------------
// K0: time-modulation scales  t1 = t_emb @ (k1r + i k1i), t2 likewise. (B,17)
// ---------------------------------------------------------------------------
__global__ void k0_tscale(const float* __restrict__ t_emb,
                          const float* __restrict__ k1r, const float* __restrict__ k1i,
                          const float* __restrict__ k2r, const float* __restrict__ k2i) {
    int b = blockIdx.x;
    int tid = threadIdx.x;           // 64 threads
    int which = tid >> 5;            // 0 -> t1, 1 -> t2
    int m = tid & 31;
    if (m >= MM) return;
    const float* kr = which ? k2r : k1r;
    const float* ki = which ? k2i : k1i;
    const float* te = t_emb + b * TDIM;
    float ar = 0.f, ai = 0.f;
    #pragma unroll 4
    for (int d = 0; d < TDIM; ++d) {
        float v = te[d];
        ar += v * kr[d * MM + m];
        ai += v * ki[d * MM + m];
    }
    g_TS[b * KY_TOT + which * MM + m] = make_float2(ar, ai);
}

// ---------------------------------------------------------------------------
// K1: partial DFT over x (real input), 17 modes, scale 1/16384.
// Pairing x <-> 128-x:  ar = v0 + sum_{x=1..63} ve[x] cos(th),
//                       ai = -sum_{x=1..63} vo[x] sin(th),
// v0 = xs0 + (-1)^kx xs64 (parity-selected).
// Contiguous per-kx twiddle rows -> zero index ALU in the inner loop.
// ---------------------------------------------------------------------------
__global__ void k1_dftx(const float* __restrict__ x) {
    __shared__ float2 sP[64 * CIN];    // (ve, vo), row 0 = (xs0+xs64, xs0-xs64). 16KB
    __shared__ float2 T1[MM * 63];     // [kx][xi-1] = (cos, sin). 8.4KB
    int b = blockIdx.x >> 7, y = blockIdx.x & 127;
    int tid = threadIdx.x;

    const float* xrow = x + (size_t)(b * GRID_N + y) * GRID_N * CIN;
    for (int i = tid; i < 64 * CIN; i += 256) {
        int xi = i >> 5, c = i & 31;
        int xp = (xi == 0) ? 64 : (128 - xi);
        float a  = xrow[xi * CIN + c];
        float bb = xrow[xp * CIN + c];
        sP[i] = make_float2(a + bb, a - bb);
    }
    for (int i = tid; i < MM * 63; i += 256) {
        int kx = i / 63, xi = i - kx * 63 + 1;
        float s, c;
        sincospif((float)(kx * xi) * (1.0f / 64.0f), &s, &c);
        T1[i] = make_float2(c, s);
    }
    __syncthreads();

    const float scale = 1.0f / 16384.0f;
    for (int idx = tid; idx < MM * CIN; idx += 256) {
        int kx = idx >> 5, c = idx & 31;
        float2 p0 = sP[c];
        float ar = (kx & 1) ? p0.y : p0.x;
        float ai = 0.f;
        const float2* T = &T1[kx * 63];
        const float2* P = &sP[CIN + c];
        #pragma unroll 9
        for (int xi = 0; xi < 63; ++xi) {
            float2 w = T[xi];           // warp-uniform broadcast
            float2 p = P[xi * CIN];
            ar += p.x * w.x;
            ai -= p.y * w.y;
        }
        g_X1[((b * MM + kx) * GRID_N + y) * CIN + c] = make_float2(ar * scale, ai * scale);
    }
}

// ---------------------------------------------------------------------------
// K2 (fused, dynamic smem): per (b, kx):
//  stage1: paired DFT over y -> 34 kept rows (18-row shared table + sign flip)
//  stage2: complex 32x32 channel mix + time scale
//  stage3: paired inverse DFT: S/D mode-pairs, E+-F output-pairs
// ---------------------------------------------------------------------------
// dynamic smem layout (bytes):
//  [0, 32768)        phase A: PA float4[64*32] (ae.re, ae.im, ao.re, ao.im)
//                    phase B aliases: sZ  float2[34*32]  at 0      (8704B)
//                                     sSD float4[17*32]  at 8704   (8704B)
//                                     T3  float2[65*17]  at 17408  (8840B)
//  [32768, 41840)    T1t float2[18*63]  (stage-1 table, rows p=0..17)
//  [41840, 50544)    sX2 float2[34*32]
//  [50544, 50816)    sT  float2[34]
#define K2_SMEM_BYTES 50816

__global__ void k2_mid(const float* __restrict__ w1r, const float* __restrict__ w1i,
                       const float* __restrict__ w2r, const float* __restrict__ w2i) {
    extern __shared__ char smemraw[];
    float4* PA  = (float4*)(smemraw);
    float2* T1t = (float2*)(smemraw + 32768);
    float2* sX2 = (float2*)(smemraw + 41840);
    float2* sT  = (float2*)(smemraw + 50544);
    float2* sZ  = (float2*)(smemraw);            // phase B
    float4* sSD = (float4*)(smemraw + 8704);     // [p-1][o]: (S.re,S.im,D.re,D.im)
    float2* T3  = (float2*)(smemraw + 17408);    // [y][p-1], y=0..64

    int b  = blockIdx.x / MM;
    int kx = blockIdx.x % MM;
    int tid = threadIdx.x;

    const float2* src = g_X1 + (size_t)(b * MM + kx) * GRID_N * CIN;
    for (int i = tid; i < 64 * CIN; i += 256) {
        int yy = i >> 5, c = i & 31;
        int yp = (yy == 0) ? 64 : (128 - yy);
        float2 a = src[yy * CIN + c];
        float2 d = src[yp * CIN + c];
        PA[i] = make_float4(a.x + d.x, a.y + d.y, a.x - d.x, a.y - d.y);
    }
    for (int i = tid; i < 18 * 63; i += 256) {
        int p = i / 63, yy = i - p * 63 + 1;
        float s, c;
        sincospif((float)(p * yy) * (1.0f / 64.0f), &s, &c);
        T1t[i] = make_float2(c, s);
    }
    if (tid < KY_TOT) sT[tid] = g_TS[b * KY_TOT + tid];
    __syncthreads();

    // ---- stage 1: DFT over y onto the 34 kept rows (paired) ----
    // A(ky) = v0 + sum_{y=1..63} [ae*cos - i*ao*sin], sin sign flips for bottom rows.
    for (int idx = tid; idx < KY_TOT * CIN; idx += 256) {
        int kyi = idx >> 5, c = idx & 31;     // warp-uniform kyi
        float4 p0 = PA[c];
        float ar, ai;
        if (kyi & 1) { ar = p0.z; ai = p0.w; } else { ar = p0.x; ai = p0.y; }
        int prow = (kyi < MM) ? kyi : (34 - kyi);
        const float2* T = &T1t[prow * 63];
        const float4* P = &PA[CIN + c];
        if (kyi < MM) {
            #pragma unroll 9
            for (int yy = 0; yy < 63; ++yy) {
                float2 w = T[yy]; float4 p = P[yy * CIN];
                ar += p.x * w.x + p.w * w.y;
                ai += p.y * w.x - p.z * w.y;
            }
        } else {  // ky = 128 - prow: cos same, sin negated
            #pragma unroll 9
            for (int yy = 0; yy < 63; ++yy) {
                float2 w = T[yy]; float4 p = P[yy * CIN];
                ar += p.x * w.x - p.w * w.y;
                ai += p.y * w.x + p.z * w.y;
            }
        }
        sX2[idx] = make_float2(ar, ai);
    }
    __syncthreads();

    // ---- stage 2: complex channel mix + time scale -> sZ (aliases PA, dead) ----
    for (int idx = tid; idx < KY_TOT * COUT; idx += 256) {
        int kyi = idx >> 5, o = idx & 31;
        const float* wr; const float* wi; int iw;
        if (kyi < MM) { wr = w1r; wi = w1i; iw = kyi; }
        else          { wr = w2r; wi = w2i; iw = kyi - MM; }
        size_t base = ((size_t)(iw * MM + kx) * CIN) * COUT + o;
        float ar = 0.f, ai = 0.f;
        #pragma unroll 8
        for (int c = 0; c < CIN; ++c) {
            float2 a = sX2[kyi * CIN + c];
            float wre = wr[base + (size_t)c * COUT];
            float wim = wi[base + (size_t)c * COUT];
            ar += a.x * wre - a.y * wim;
            ai += a.x * wim + a.y * wre;
        }
        float2 ts = sT[kyi];
        sZ[idx] = make_float2(ar * ts.x - ai * ts.y, ar * ts.y + ai * ts.x);
    }
    // stage-3 table (aliases dead PA region; disjoint from sZ/sX2)
    for (int i = tid; i < 65 * MM; i += 256) {
        int yy = i / MM, p = i - yy * MM + 1;
        float s, c;
        sincospif((float)(p * yy) * (1.0f / 64.0f), &s, &c);
        T3[i] = make_float2(c, s);
    }
    __syncthreads();

    // ---- S/D mode pairs: p=1..16 pair (p, 34-p); p=17 unpaired (ky=111) ----
    for (int i = tid; i < MM * 32; i += 256) {
        int p = (i >> 5) + 1, o = i & 31;
        float2 zp = sZ[p * COUT + o];
        float4 sd;
        if (p < MM) {
            float2 zq = sZ[(34 - p) * COUT + o];
            sd = make_float4(zp.x + zq.x, zp.y + zq.y, zp.x - zq.x, zp.y - zq.y);
        } else {
            sd = make_float4(zp.x, zp.y, -zp.x, -zp.y);
        }
        sSD[i] = sd;
    }
    __syncthreads();

    // ---- stage 3: Y[y] = E + F, Y[128-y] = E - F ----
    {
        int o = tid & 31, yg = tid >> 5;
        float2 z0 = sZ[o];
        for (int yy = yg; yy <= 64; yy += 8) {
            float er = z0.x, ei = z0.y, fr = 0.f, fi = 0.f;
            const float2* T  = &T3[yy * MM];
            const float4* SD = &sSD[o];
            #pragma unroll
            for (int p = 0; p < MM; ++p) {
                float2 w  = T[p];        // warp-uniform
                float4 sd = SD[p * 32];
                er += sd.x * w.x;  ei += sd.y * w.x;
                fr -= sd.w * w.y;  fi += sd.z * w.y;
            }
            g_Y1[(((size_t)b * GRID_N + yy) * MM + kx) * COUT + o] =
                make_float2(er + fr, ei + fi);
            if (yy >= 1 && yy < 64)
                g_Y1[(((size_t)b * GRID_N + (128 - yy)) * MM + kx) * COUT + o] =
                    make_float2(er - fr, ei - fi);
        }
    }
}

// ---------------------------------------------------------------------------
// K3: inverse over x with irfft (C2R) semantics, output pairing:
//   E = yr0 + sum yr[k] cos,  O = -sum yi[k] sin
//   out[x] = E+O,  out[128-x] = E-O
// ---------------------------------------------------------------------------
__global__ void k3_idftx(float* __restrict__ out) {
    __shared__ float2 sY[MM * COUT];   // 4.25 KB
    __shared__ float2 T3[65 * 16];     // [x][k-1], 8.3 KB
    int b = blockIdx.x >> 7, y = blockIdx.x & 127;
    int tid = threadIdx.x;

    const float2* src = g_Y1 + (size_t)(b * GRID_N + y) * MM * COUT;
    for (int i = tid; i < MM * COUT; i += 256) sY[i] = src[i];
    for (int i = tid; i < 65 * 16; i += 256) {
        int xx = i >> 4, k = (i & 15) + 1;
        float s, c;
        sincospif((float)(k * xx) * (1.0f / 64.0f), &s, &c);
        T3[i] = make_float2(c, s);
    }
    __syncthreads();

    int o  = tid & 31;
    int xg = tid >> 5;   // 0..7

    float yr[MM], yi[MM];
    yr[0] = sY[o].x;     // Im of bin 0 ignored (C2R); bin 64 is zero
    yi[0] = 0.f;
    #pragma unroll
    for (int k = 1; k < MM; ++k) {
        float2 v = sY[k * COUT + o];
        yr[k] = 2.f * v.x;
        yi[k] = 2.f * v.y;
    }

    float* orow = out + (size_t)(b * GRID_N + y) * GRID_N * COUT;
    for (int xx = xg; xx <= 64; xx += 8) {
        float E = yr[0], O = 0.f;
        const float2* T = &T3[xx * 16];
        #pragma unroll
        for (int k = 1; k < MM; ++k) {
            float2 w = T[k - 1];       // warp-uniform, immediate offsets
            E += yr[k] * w.x;
            O -= yi[k] * w.y;
        }
        orow[(size_t)xx * COUT + o] = E + O;
        if (xx >= 1 && xx < 64)
            orow[(size_t)(128 - xx) * COUT + o] = E - O;
    }
}

// ---------------------------------------------------------------------------
extern "C" void kernel_launch(void* const* d_in, const int* in_sizes, int n_in,
                              void* d_out, int out_size) {
    const float* x     = (const float*)d_in[0];
    const float* t_emb = (const float*)d_in[1];
    const float* w1r   = (const float*)d_in[2];
    const float* w1i   = (const float*)d_in[3];
    const float* w2r   = (const float*)d_in[4];
    const float* w2i   = (const float*)d_in[5];
    const float* k1r   = (const float*)d_in[6];
    const float* k1i   = (const float*)d_in[7];
    const float* k2r   = (const float*)d_in[8];
    const float* k2i   = (const float*)d_in[9];
    float* out = (float*)d_out;

    cudaFuncSetAttribute(k2_mid, cudaFuncAttributeMaxDynamicSharedMemorySize,
                         K2_SMEM_BYTES);

    k0_tscale<<<NB, 64>>>(t_emb, k1r, k1i, k2r, k2i);
    k1_dftx  <<<NB * GRID_N, 256>>>(x);
    k2_mid   <<<NB * MM, 256, K2_SMEM_BYTES>>>(w1r, w1i, w2r, w2i);
    k3_idftx <<<NB * GRID_N, 256>>>(out);
}